// round 2
// baseline (speedup 1.0000x reference)
#include <cuda_runtime.h>

#define N_NODES 100000
#define N_EDGES 3200000
#define IN_DIM 128
#define HID 64
#define N_GRAPHS 512

// ---- scratch (static device globals; no allocation allowed) ----
__device__ float g_xw[N_NODES * HID];     // x @ W_gcn
__device__ float g_z[N_NODES * HID];      // aggregated messages
__device__ float g_deg[N_NODES];
__device__ float g_dinv[N_NODES];
__device__ float g_sums[N_GRAPHS * HID];
__device__ float g_cnts[N_GRAPHS];

__device__ __forceinline__ void red_add_v4(float* p, float4 v) {
    asm volatile("red.global.add.v4.f32 [%0], {%1,%2,%3,%4};"
                 :: "l"(p), "f"(v.x), "f"(v.y), "f"(v.z), "f"(v.w) : "memory");
}

// ---- init: deg=1 (self-loop), zero pool accumulators ----
__global__ void init_kernel() {
    int i = blockIdx.x * blockDim.x + threadIdx.x;
    if (i < N_NODES) g_deg[i] = 1.0f;
    if (i < N_GRAPHS * HID) g_sums[i] = 0.0f;
    if (i < N_GRAPHS) g_cnts[i] = 0.0f;
}

// ---- in-degree over target nodes (col = edge_index[1]) ----
__global__ void deg_kernel(const int* __restrict__ ei) {
    int e = blockIdx.x * blockDim.x + threadIdx.x;
    if (e < N_EDGES) atomicAdd(&g_deg[ei[N_EDGES + e]], 1.0f);
}

__global__ void dinv_kernel() {
    int i = blockIdx.x * blockDim.x + threadIdx.x;
    if (i < N_NODES) g_dinv[i] = rsqrtf(g_deg[i]);  // deg >= 1 always
}

// ---- GEMM: xw = x @ W_gcn; epilogue writes z = dinv^2 * xw (self-loop term) ----
// W (128x64, 32KB) in shared; x streamed via half-warp-broadcast LDG.
// 256 threads; thread t -> 2 rows (t>>4), 4 cols ((t&15)*4); 32 rows/block.
__global__ __launch_bounds__(256) void gemm_kernel(const float* __restrict__ x,
                                                   const float* __restrict__ W) {
    __shared__ float Ws[IN_DIM][HID];   // 32 KB

    const int tid = threadIdx.x;
    for (int i = tid; i < (IN_DIM * HID) / 4; i += 256)
        ((float4*)Ws)[i] = ((const float4*)W)[i];
    __syncthreads();

    const int tc = (tid & 15) * 4;
    const int r0 = blockIdx.x * 32 + (tid >> 4) * 2;
    const int r1 = r0 + 1;
    if (r0 >= N_NODES) return;
    const bool has1 = (r1 < N_NODES);

    const float4* x0 = (const float4*)(x + (size_t)r0 * IN_DIM);
    const float4* x1 = (const float4*)(x + (size_t)(has1 ? r1 : r0) * IN_DIM);

    float4 a0 = make_float4(0.f,0.f,0.f,0.f), a1 = a0;

    #pragma unroll 4
    for (int k4 = 0; k4 < IN_DIM / 4; k4++) {
        float4 v0 = __ldg(&x0[k4]);
        float4 v1 = __ldg(&x1[k4]);
        const float* wrow = &Ws[k4 * 4][tc];
        #pragma unroll
        for (int j = 0; j < 4; j++) {
            float4 w = *(const float4*)(wrow + j * HID);
            float s0 = ((const float*)&v0)[j];
            float s1 = ((const float*)&v1)[j];
            a0.x += s0 * w.x; a0.y += s0 * w.y; a0.z += s0 * w.z; a0.w += s0 * w.w;
            a1.x += s1 * w.x; a1.y += s1 * w.y; a1.z += s1 * w.z; a1.w += s1 * w.w;
        }
    }

    {
        float d = g_dinv[r0], nrm = d * d;
        *(float4*)&g_xw[(size_t)r0 * HID + tc] = a0;
        *(float4*)&g_z [(size_t)r0 * HID + tc] =
            make_float4(a0.x * nrm, a0.y * nrm, a0.z * nrm, a0.w * nrm);
    }
    if (has1) {
        float d = g_dinv[r1], nrm = d * d;
        *(float4*)&g_xw[(size_t)r1 * HID + tc] = a1;
        *(float4*)&g_z [(size_t)r1 * HID + tc] =
            make_float4(a1.x * nrm, a1.y * nrm, a1.z * nrm, a1.w * nrm);
    }
}

// ---- edge scatter: 2 edges per warp (16 lanes x float4 each) ----
__global__ __launch_bounds__(256) void edge_kernel(const int* __restrict__ ei) {
    unsigned warp = blockIdx.x * 8u + (threadIdx.x >> 5);
    int lane = threadIdx.x & 31;
    unsigned e = warp * 2u + (lane >> 4);
    if (e >= N_EDGES) return;
    int sub = lane & 15;

    int r = 0, c = 0;
    float norm = 0.f;
    if (sub == 0) {
        r = __ldg(&ei[e]);
        c = __ldg(&ei[N_EDGES + e]);
        norm = g_dinv[r] * g_dinv[c];
    }
    int src = lane & 16;  // broadcast from lane 0 or 16
    r    = __shfl_sync(0xffffffffu, r, src);
    c    = __shfl_sync(0xffffffffu, c, src);
    norm = __shfl_sync(0xffffffffu, norm, src);

    float4 v = ((const float4*)g_xw)[(size_t)r * 16 + sub];
    v.x *= norm; v.y *= norm; v.z *= norm; v.w *= norm;
    red_add_v4(&g_z[(size_t)c * HID + sub * 4], v);
}

// ---- relu(z + b_gcn) + global mean pool: 2 nodes per warp ----
__global__ __launch_bounds__(256) void pool_kernel(const int* __restrict__ batch,
                                                   const float* __restrict__ b_gcn) {
    unsigned warp = blockIdx.x * 8u + (threadIdx.x >> 5);
    int lane = threadIdx.x & 31;
    unsigned node = warp * 2u + (lane >> 4);
    if (node >= N_NODES) return;
    int sub = lane & 15;

    int g = 0;
    if (sub == 0) g = __ldg(&batch[node]);
    g = __shfl_sync(0xffffffffu, g, lane & 16);

    float4 z = ((const float4*)g_z)[(size_t)node * 16 + sub];
    float4 b = ((const float4*)b_gcn)[sub];
    float4 v = make_float4(fmaxf(z.x + b.x, 0.f), fmaxf(z.y + b.y, 0.f),
                           fmaxf(z.z + b.z, 0.f), fmaxf(z.w + b.w, 0.f));
    red_add_v4(&g_sums[(size_t)g * HID + sub * 4], v);
    if (sub == 0) atomicAdd(&g_cnts[g], 1.0f);
}

// ---- per-graph MLP: relu(g@W1+b1) @ W2 + b2 -> sigmoid ----
__global__ __launch_bounds__(64) void mlp_kernel(const float* __restrict__ W1,
                                                 const float* __restrict__ b1,
                                                 const float* __restrict__ W2,
                                                 const float* __restrict__ b2,
                                                 float* __restrict__ out) {
    int g = blockIdx.x;
    int c = threadIdx.x;
    __shared__ float gs[HID], hs[HID];

    float cnt = fmaxf(g_cnts[g], 1.0f);
    gs[c] = g_sums[(size_t)g * HID + c] / cnt;
    __syncthreads();

    float acc = b1[c];
    #pragma unroll 8
    for (int k = 0; k < HID; k++) acc += gs[k] * W1[k * HID + c];
    hs[c] = fmaxf(acc, 0.0f);
    __syncthreads();

    if (c < 2) {
        float a = b2[c];
        #pragma unroll 8
        for (int k = 0; k < HID; k++) a += hs[k] * W2[k * 2 + c];
        out[(size_t)g * 2 + c] = 1.0f / (1.0f + expf(-a));
    }
}

extern "C" void kernel_launch(void* const* d_in, const int* in_sizes, int n_in,
                              void* d_out, int out_size) {
    const float* x     = (const float*)d_in[0];
    const int*   ei    = (const int*)d_in[1];
    const int*   batch = (const int*)d_in[2];
    const float* W_gcn = (const float*)d_in[3];
    const float* b_gcn = (const float*)d_in[4];
    const float* W1    = (const float*)d_in[5];
    const float* b1    = (const float*)d_in[6];
    const float* W2    = (const float*)d_in[7];
    const float* b2    = (const float*)d_in[8];
    float*       out   = (float*)d_out;

    init_kernel<<<(N_NODES + 255) / 256, 256>>>();
    deg_kernel<<<(N_EDGES + 255) / 256, 256>>>(ei);
    dinv_kernel<<<(N_NODES + 255) / 256, 256>>>();
    gemm_kernel<<<(N_NODES + 31) / 32, 256>>>(x, W_gcn);
    edge_kernel<<<((N_EDGES + 1) / 2 + 7) / 8, 256>>>(ei);
    pool_kernel<<<((N_NODES + 1) / 2 + 7) / 8, 256>>>(batch, b_gcn);
    mlp_kernel<<<N_GRAPHS, 64>>>(W1, b1, W2, b2, out);
}

// round 3
// speedup vs baseline: 1.1759x; 1.1759x over previous
#include <cuda_runtime.h>
#include <cuda_fp16.h>

#define N_NODES 100000
#define N_EDGES 3200000
#define IN_DIM 128
#define HID 64
#define N_GRAPHS 512

// ---- scratch (static device globals; no allocation allowed) ----
__device__ __half g_xw_h[N_NODES * HID];  // x @ W_gcn in fp16 (message matrix)
__device__ float  g_z[N_NODES * HID];     // aggregated messages (fp32)
__device__ float  g_deg[N_NODES];
__device__ float  g_dinv[N_NODES];
__device__ float  g_sums[N_GRAPHS * HID];
__device__ float  g_cnts[N_GRAPHS];

__device__ __forceinline__ void red_add_v4(float* p, float4 v) {
    asm volatile("red.global.add.v4.f32 [%0], {%1,%2,%3,%4};"
                 :: "l"(p), "f"(v.x), "f"(v.y), "f"(v.z), "f"(v.w) : "memory");
}

// ---- init: deg=1 (self-loop), zero pool accumulators ----
__global__ void init_kernel() {
    int i = blockIdx.x * blockDim.x + threadIdx.x;
    if (i < N_NODES) g_deg[i] = 1.0f;
    if (i < N_GRAPHS * HID) g_sums[i] = 0.0f;
    if (i < N_GRAPHS) g_cnts[i] = 0.0f;
}

// ---- in-degree over target nodes, 4 edges per thread ----
__global__ void deg_kernel(const int* __restrict__ ei) {
    int i = blockIdx.x * blockDim.x + threadIdx.x;
    if (i < N_EDGES / 4) {
        int4 c = ((const int4*)(ei + N_EDGES))[i];
        atomicAdd(&g_deg[c.x], 1.0f);
        atomicAdd(&g_deg[c.y], 1.0f);
        atomicAdd(&g_deg[c.z], 1.0f);
        atomicAdd(&g_deg[c.w], 1.0f);
    }
}

__global__ void dinv_kernel() {
    int i = blockIdx.x * blockDim.x + threadIdx.x;
    if (i < N_NODES) g_dinv[i] = rsqrtf(g_deg[i]);  // deg >= 1 always
}

// ---- GEMM: xw = x @ W_gcn (fp16 out); z = dinv^2 * xw (fp32, self-loop term) ----
// Block: 256 threads, tile 128 rows x 64 cols, thread = 8 rows x 4 cols.
// x tile stored K-MAJOR in shared so inner loop is pure LDS.128 broadcast.
__global__ __launch_bounds__(256) void gemm_kernel(const float* __restrict__ x,
                                                   const float* __restrict__ W) {
    __shared__ float xs[32][132];  // k-major x chunk, padded stride
    __shared__ float Wc[32][HID];  // W chunk

    const int tid  = threadIdx.x;
    const int row0 = blockIdx.x * 128;
    const int tc   = (tid & 15) * 4;   // col base
    const int tr   = (tid >> 4) * 8;   // row base

    const int  lr    = tid >> 1;       // loader: row 0..127
    const int  lhalf = tid & 1;        // loader: which 16-float half of the chunk
    const bool rowok = (row0 + lr) < N_NODES;
    const float* xrow = x + (size_t)(row0 + lr) * IN_DIM;

    float acc[8][4] = {};

    #pragma unroll
    for (int kc = 0; kc < 4; kc++) {
        __syncthreads();
        // load x chunk transposed: xs[k][row]
        const float4* src = (const float4*)(xrow + kc * 32 + lhalf * 16);
        #pragma unroll
        for (int j = 0; j < 4; j++) {
            float4 v = rowok ? __ldg(&src[j]) : make_float4(0.f, 0.f, 0.f, 0.f);
            int kl = lhalf * 16 + j * 4;
            xs[kl + 0][lr] = v.x; xs[kl + 1][lr] = v.y;
            xs[kl + 2][lr] = v.z; xs[kl + 3][lr] = v.w;
        }
        // load W chunk (32x64 = 512 float4)
        #pragma unroll
        for (int t = 0; t < 2; t++) {
            int idx = tid + t * 256;
            int k = idx >> 4, c4 = idx & 15;
            *(float4*)&Wc[k][c4 * 4] = __ldg(&((const float4*)W)[(kc * 32 + k) * 16 + c4]);
        }
        __syncthreads();

        #pragma unroll 8
        for (int k = 0; k < 32; k++) {
            float4 w  = *(const float4*)&Wc[k][tc];
            float4 xa = *(const float4*)&xs[k][tr];
            float4 xb = *(const float4*)&xs[k][tr + 4];
            float xv[8] = {xa.x, xa.y, xa.z, xa.w, xb.x, xb.y, xb.z, xb.w};
            #pragma unroll
            for (int i = 0; i < 8; i++) {
                acc[i][0] += xv[i] * w.x;
                acc[i][1] += xv[i] * w.y;
                acc[i][2] += xv[i] * w.z;
                acc[i][3] += xv[i] * w.w;
            }
        }
    }

    #pragma unroll
    for (int i = 0; i < 8; i++) {
        int gr = row0 + tr + i;
        if (gr < N_NODES) {
            float d = g_dinv[gr], nrm = d * d;
            *(float4*)&g_z[(size_t)gr * HID + tc] =
                make_float4(acc[i][0] * nrm, acc[i][1] * nrm,
                            acc[i][2] * nrm, acc[i][3] * nrm);
            __half2 h0 = __floats2half2_rn(acc[i][0], acc[i][1]);
            __half2 h1 = __floats2half2_rn(acc[i][2], acc[i][3]);
            uint2 packed = make_uint2(*(unsigned*)&h0, *(unsigned*)&h1);
            *(uint2*)&g_xw_h[(size_t)gr * HID + tc] = packed;
        }
    }
}

// ---- edge scatter: 2 edges per warp; gather fp16 row, fp32 vector RED ----
__global__ __launch_bounds__(256) void edge_kernel(const int* __restrict__ ei) {
    unsigned warp = blockIdx.x * 8u + (threadIdx.x >> 5);
    int lane = threadIdx.x & 31;
    unsigned e = warp * 2u + (lane >> 4);
    if (e >= N_EDGES) return;
    int sub = lane & 15;

    int r = 0, c = 0;
    float norm = 0.f;
    if (sub == 0) {
        r = __ldg(&ei[e]);
        c = __ldg(&ei[N_EDGES + e]);
        norm = g_dinv[r] * g_dinv[c];
    }
    int src = lane & 16;
    r    = __shfl_sync(0xffffffffu, r, src);
    c    = __shfl_sync(0xffffffffu, c, src);
    norm = __shfl_sync(0xffffffffu, norm, src);

    uint2 raw = *(const uint2*)(g_xw_h + (size_t)r * HID + sub * 4);
    float2 f0 = __half22float2(*(__half2*)&raw.x);
    float2 f1 = __half22float2(*(__half2*)&raw.y);
    float4 v = make_float4(f0.x * norm, f0.y * norm, f1.x * norm, f1.y * norm);
    red_add_v4(&g_z[(size_t)c * HID + sub * 4], v);
}

// ---- relu(z + b_gcn) + mean-pool accumulate; exploits sorted batch ----
// 256 threads: 4 node-lanes x 64 cols; each thread scans 16 consecutive nodes,
// accumulating in a register, flushing one atomic per graph boundary.
__global__ __launch_bounds__(256) void pool_kernel(const int* __restrict__ batch,
                                                   const float* __restrict__ b_gcn) {
    int c     = threadIdx.x & 63;
    int seg   = threadIdx.x >> 6;
    int nbase = blockIdx.x * 64 + seg * 16;
    float b   = __ldg(&b_gcn[c]);

    float acc = 0.f;
    int curg = -1, cnt = 0;
    for (int it = 0; it < 16; it++) {
        int node = nbase + it;
        if (node >= N_NODES) break;
        int g = __ldg(&batch[node]);
        if (g != curg) {
            if (curg >= 0) {
                atomicAdd(&g_sums[(size_t)curg * HID + c], acc);
                if (c == 0) atomicAdd(&g_cnts[curg], (float)cnt);
            }
            acc = 0.f; cnt = 0; curg = g;
        }
        acc += fmaxf(g_z[(size_t)node * HID + c] + b, 0.f);
        cnt++;
    }
    if (curg >= 0) {
        atomicAdd(&g_sums[(size_t)curg * HID + c], acc);
        if (c == 0) atomicAdd(&g_cnts[curg], (float)cnt);
    }
}

// ---- per-graph MLP: relu(g@W1+b1) @ W2 + b2 -> sigmoid ----
__global__ __launch_bounds__(64) void mlp_kernel(const float* __restrict__ W1,
                                                 const float* __restrict__ b1,
                                                 const float* __restrict__ W2,
                                                 const float* __restrict__ b2,
                                                 float* __restrict__ out) {
    int g = blockIdx.x;
    int c = threadIdx.x;
    __shared__ float gs[HID], hs[HID];

    float cnt = fmaxf(g_cnts[g], 1.0f);
    gs[c] = g_sums[(size_t)g * HID + c] / cnt;
    __syncthreads();

    float acc = b1[c];
    #pragma unroll 8
    for (int k = 0; k < HID; k++) acc += gs[k] * W1[k * HID + c];
    hs[c] = fmaxf(acc, 0.0f);
    __syncthreads();

    if (c < 2) {
        float a = b2[c];
        #pragma unroll 8
        for (int k = 0; k < HID; k++) a += hs[k] * W2[k * 2 + c];
        out[(size_t)g * 2 + c] = 1.0f / (1.0f + expf(-a));
    }
}

extern "C" void kernel_launch(void* const* d_in, const int* in_sizes, int n_in,
                              void* d_out, int out_size) {
    const float* x     = (const float*)d_in[0];
    const int*   ei    = (const int*)d_in[1];
    const int*   batch = (const int*)d_in[2];
    const float* W_gcn = (const float*)d_in[3];
    const float* b_gcn = (const float*)d_in[4];
    const float* W1    = (const float*)d_in[5];
    const float* b1    = (const float*)d_in[6];
    const float* W2    = (const float*)d_in[7];
    const float* b2    = (const float*)d_in[8];
    float*       out   = (float*)d_out;

    init_kernel<<<(N_NODES + 255) / 256, 256>>>();
    deg_kernel<<<(N_EDGES / 4 + 255) / 256, 256>>>(ei);
    dinv_kernel<<<(N_NODES + 255) / 256, 256>>>();
    gemm_kernel<<<(N_NODES + 127) / 128, 256>>>(x, W_gcn);
    edge_kernel<<<((N_EDGES + 1) / 2 + 7) / 8, 256>>>(ei);
    pool_kernel<<<(N_NODES + 63) / 64, 256>>>(batch, b_gcn);
    mlp_kernel<<<N_GRAPHS, 64>>>(W1, b1, W2, b2, out);
}

// round 4
// speedup vs baseline: 1.5113x; 1.2853x over previous
#include <cuda_runtime.h>
#include <cuda_fp16.h>

#define N_NODES 100000
#define N_EDGES 3200000
#define IN_DIM 128
#define HID 64
#define N_GRAPHS 512
#define N_SBLK 98   // ceil(N_NODES / 1024)

// ---- scratch (static device globals; no allocation allowed) ----
__device__ __half g_xw_h[N_NODES * HID];  // x @ W_gcn in fp16 (message matrix)
__device__ float  g_dinv[N_NODES];
__device__ int    g_ecnt[N_NODES];        // in-degree (excl. self-loop)
__device__ int    g_off[N_NODES];         // CSR offsets (exclusive scan of ecnt)
__device__ int    g_cursor[N_NODES];      // scatter cursors
__device__ int    g_bsum[N_SBLK];         // scan block sums
__device__ uint2  g_packed[N_EDGES];      // per-edge (src, norm) sorted by target
__device__ float  g_sums[N_GRAPHS * HID];
__device__ float  g_cnts[N_GRAPHS];

__device__ __forceinline__ void red_add_v2(float* p, float2 v) {
    asm volatile("red.global.add.v2.f32 [%0], {%1,%2};"
                 :: "l"(p), "f"(v.x), "f"(v.y) : "memory");
}

// ---- init: zero counts + pool accumulators ----
__global__ void init_kernel() {
    int i = blockIdx.x * blockDim.x + threadIdx.x;
    if (i < N_NODES) g_ecnt[i] = 0;
    if (i < N_GRAPHS * HID) g_sums[i] = 0.0f;
    if (i < N_GRAPHS) g_cnts[i] = 0.0f;
}

// ---- in-degree over target nodes, 4 edges per thread ----
__global__ void deg_kernel(const int* __restrict__ ei) {
    int i = blockIdx.x * blockDim.x + threadIdx.x;
    if (i < N_EDGES / 4) {
        int4 c = ((const int4*)(ei + N_EDGES))[i];
        atomicAdd(&g_ecnt[c.x], 1);
        atomicAdd(&g_ecnt[c.y], 1);
        atomicAdd(&g_ecnt[c.z], 1);
        atomicAdd(&g_ecnt[c.w], 1);
    }
}

__global__ void dinv_kernel() {
    int i = blockIdx.x * blockDim.x + threadIdx.x;
    if (i < N_NODES) g_dinv[i] = rsqrtf(1.0f + (float)g_ecnt[i]);  // +1 self-loop
}

// ---- prefix scan of g_ecnt -> g_off (3 stages) ----
__global__ __launch_bounds__(1024) void scan1_kernel() {
    __shared__ int sh[1024];
    int i = blockIdx.x * 1024 + threadIdx.x;
    sh[threadIdx.x] = (i < N_NODES) ? g_ecnt[i] : 0;
    __syncthreads();
    for (int d = 512; d > 0; d >>= 1) {
        if (threadIdx.x < d) sh[threadIdx.x] += sh[threadIdx.x + d];
        __syncthreads();
    }
    if (threadIdx.x == 0) g_bsum[blockIdx.x] = sh[0];
}

__global__ __launch_bounds__(128) void scan2_kernel() {
    __shared__ int sh[128];
    int t = threadIdx.x;
    int v = (t < N_SBLK) ? g_bsum[t] : 0;
    sh[t] = v;
    __syncthreads();
    for (int d = 1; d < 128; d <<= 1) {
        int tmp = (t >= d) ? sh[t - d] : 0;
        __syncthreads();
        sh[t] += tmp;
        __syncthreads();
    }
    if (t < N_SBLK) g_bsum[t] = sh[t] - v;  // exclusive base
}

__global__ __launch_bounds__(1024) void scan3_kernel() {
    __shared__ int sh[1024];
    int i = blockIdx.x * 1024 + threadIdx.x;
    int v = (i < N_NODES) ? g_ecnt[i] : 0;
    sh[threadIdx.x] = v;
    __syncthreads();
    for (int d = 1; d < 1024; d <<= 1) {
        int tmp = (threadIdx.x >= d) ? sh[threadIdx.x - d] : 0;
        __syncthreads();
        sh[threadIdx.x] += tmp;
        __syncthreads();
    }
    if (i < N_NODES) {
        int off = g_bsum[blockIdx.x] + sh[threadIdx.x] - v;
        g_off[i] = off;
        g_cursor[i] = off;
    }
}

// ---- scatter edges into CSR buckets: packed (src, norm) ----
__global__ void scatter_kernel(const int* __restrict__ ei) {
    int e = blockIdx.x * blockDim.x + threadIdx.x;
    if (e >= N_EDGES) return;
    int r = __ldg(&ei[e]);
    int c = __ldg(&ei[N_EDGES + e]);
    float norm = g_dinv[r] * g_dinv[c];
    int pos = atomicAdd(&g_cursor[c], 1);
    g_packed[pos] = make_uint2((unsigned)r, __float_as_uint(norm));
}

// ---- GEMM: xw = x @ W_gcn, fp16 output only ----
// Block: 256 threads, tile 128 rows x 64 cols, thread = 8 rows x 4 cols.
__global__ __launch_bounds__(256) void gemm_kernel(const float* __restrict__ x,
                                                   const float* __restrict__ W) {
    __shared__ float xs[32][132];  // k-major x chunk, padded stride
    __shared__ float Wc[32][HID];

    const int tid  = threadIdx.x;
    const int row0 = blockIdx.x * 128;
    const int tc   = (tid & 15) * 4;
    const int tr   = (tid >> 4) * 8;

    const int  lr    = tid >> 1;
    const int  lhalf = tid & 1;
    const bool rowok = (row0 + lr) < N_NODES;
    const float* xrow = x + (size_t)(row0 + lr) * IN_DIM;

    float acc[8][4] = {};

    #pragma unroll
    for (int kc = 0; kc < 4; kc++) {
        __syncthreads();
        const float4* src = (const float4*)(xrow + kc * 32 + lhalf * 16);
        #pragma unroll
        for (int j = 0; j < 4; j++) {
            float4 v = rowok ? __ldg(&src[j]) : make_float4(0.f, 0.f, 0.f, 0.f);
            int kl = lhalf * 16 + j * 4;
            xs[kl + 0][lr] = v.x; xs[kl + 1][lr] = v.y;
            xs[kl + 2][lr] = v.z; xs[kl + 3][lr] = v.w;
        }
        #pragma unroll
        for (int t = 0; t < 2; t++) {
            int idx = tid + t * 256;
            int k = idx >> 4, c4 = idx & 15;
            *(float4*)&Wc[k][c4 * 4] = __ldg(&((const float4*)W)[(kc * 32 + k) * 16 + c4]);
        }
        __syncthreads();

        #pragma unroll 8
        for (int k = 0; k < 32; k++) {
            float4 w  = *(const float4*)&Wc[k][tc];
            float4 xa = *(const float4*)&xs[k][tr];
            float4 xb = *(const float4*)&xs[k][tr + 4];
            float xv[8] = {xa.x, xa.y, xa.z, xa.w, xb.x, xb.y, xb.z, xb.w};
            #pragma unroll
            for (int i = 0; i < 8; i++) {
                acc[i][0] += xv[i] * w.x;
                acc[i][1] += xv[i] * w.y;
                acc[i][2] += xv[i] * w.z;
                acc[i][3] += xv[i] * w.w;
            }
        }
    }

    #pragma unroll
    for (int i = 0; i < 8; i++) {
        int gr = row0 + tr + i;
        if (gr < N_NODES) {
            __half2 h0 = __floats2half2_rn(acc[i][0], acc[i][1]);
            __half2 h1 = __floats2half2_rn(acc[i][2], acc[i][3]);
            uint2 packed = make_uint2(*(unsigned*)&h0, *(unsigned*)&h1);
            *(uint2*)&g_xw_h[(size_t)gr * HID + tc] = packed;
        }
    }
}

// ---- aggregate + bias + relu + mean-pool fused; warp per node ----
__global__ __launch_bounds__(256) void aggregate_kernel(const int* __restrict__ batch,
                                                        const float* __restrict__ b_gcn) {
    int n = blockIdx.x * 8 + (threadIdx.x >> 5);
    int lane = threadIdx.x & 31;
    if (n >= N_NODES) return;

    int   start = __ldg(&g_off[n]);
    int   cnt   = __ldg(&g_ecnt[n]);
    float dc    = g_dinv[n];

    // self-loop init: dinv^2 * xw[n]
    unsigned sv = __ldg((const unsigned*)(g_xw_h + ((size_t)n << 6)) + lane);
    float2 acc = __half22float2(*(__half2*)&sv);
    float sl = dc * dc;
    acc.x *= sl; acc.y *= sl;

    for (int base = 0; base < cnt; base += 32) {
        int m = cnt - base; if (m > 32) m = 32;
        uint2 pk = make_uint2(0u, 0u);
        if (lane < m) pk = __ldg(&g_packed[start + base + lane]);
        if (m == 32) {
            #pragma unroll
            for (int j = 0; j < 32; j++) {
                int   r  = __shfl_sync(0xffffffffu, (int)pk.x, j);
                float nm = __uint_as_float(__shfl_sync(0xffffffffu, pk.y, j));
                unsigned rv = __ldg((const unsigned*)(g_xw_h + ((size_t)r << 6)) + lane);
                float2 f = __half22float2(*(__half2*)&rv);
                acc.x += f.x * nm; acc.y += f.y * nm;
            }
        } else {
            for (int j = 0; j < m; j++) {
                int   r  = __shfl_sync(0xffffffffu, (int)pk.x, j);
                float nm = __uint_as_float(__shfl_sync(0xffffffffu, pk.y, j));
                unsigned rv = __ldg((const unsigned*)(g_xw_h + ((size_t)r << 6)) + lane);
                float2 f = __half22float2(*(__half2*)&rv);
                acc.x += f.x * nm; acc.y += f.y * nm;
            }
        }
    }

    float2 b = __ldg(&((const float2*)b_gcn)[lane]);
    acc.x = fmaxf(acc.x + b.x, 0.0f);
    acc.y = fmaxf(acc.y + b.y, 0.0f);

    int g = __ldg(&batch[n]);
    red_add_v2(&g_sums[(size_t)g * HID + lane * 2], acc);
    if (lane == 0) atomicAdd(&g_cnts[g], 1.0f);
}

// ---- per-graph MLP: relu(g@W1+b1) @ W2 + b2 -> sigmoid ----
__global__ __launch_bounds__(64) void mlp_kernel(const float* __restrict__ W1,
                                                 const float* __restrict__ b1,
                                                 const float* __restrict__ W2,
                                                 const float* __restrict__ b2,
                                                 float* __restrict__ out) {
    int g = blockIdx.x;
    int c = threadIdx.x;
    __shared__ float gs[HID], hs[HID];

    float cnt = fmaxf(g_cnts[g], 1.0f);
    gs[c] = g_sums[(size_t)g * HID + c] / cnt;
    __syncthreads();

    float acc = b1[c];
    #pragma unroll 8
    for (int k = 0; k < HID; k++) acc += gs[k] * W1[k * HID + c];
    hs[c] = fmaxf(acc, 0.0f);
    __syncthreads();

    if (c < 2) {
        float a = b2[c];
        #pragma unroll 8
        for (int k = 0; k < HID; k++) a += hs[k] * W2[k * 2 + c];
        out[(size_t)g * 2 + c] = 1.0f / (1.0f + expf(-a));
    }
}

extern "C" void kernel_launch(void* const* d_in, const int* in_sizes, int n_in,
                              void* d_out, int out_size) {
    const float* x     = (const float*)d_in[0];
    const int*   ei    = (const int*)d_in[1];
    const int*   batch = (const int*)d_in[2];
    const float* W_gcn = (const float*)d_in[3];
    const float* b_gcn = (const float*)d_in[4];
    const float* W1    = (const float*)d_in[5];
    const float* b1    = (const float*)d_in[6];
    const float* W2    = (const float*)d_in[7];
    const float* b2    = (const float*)d_in[8];
    float*       out   = (float*)d_out;

    init_kernel<<<(N_NODES + 255) / 256, 256>>>();
    deg_kernel<<<(N_EDGES / 4 + 255) / 256, 256>>>(ei);
    dinv_kernel<<<(N_NODES + 255) / 256, 256>>>();
    scan1_kernel<<<N_SBLK, 1024>>>();
    scan2_kernel<<<1, 128>>>();
    scan3_kernel<<<N_SBLK, 1024>>>();
    scatter_kernel<<<(N_EDGES + 255) / 256, 256>>>(ei);
    gemm_kernel<<<(N_NODES + 127) / 128, 256>>>(x, W_gcn);
    aggregate_kernel<<<(N_NODES + 7) / 8, 256>>>(batch, b_gcn);
    mlp_kernel<<<N_GRAPHS, 64>>>(W1, b1, W2, b2, out);
}

// round 5
// speedup vs baseline: 1.6226x; 1.0737x over previous
#include <cuda_runtime.h>
#include <cuda_fp16.h>

#define N_NODES 100000
#define N_EDGES 3200000
#define IN_DIM 128
#define HID 64
#define N_GRAPHS 512
#define N_SBLK 98   // ceil(N_NODES / 1024)

// ---- scratch (static device globals; no allocation allowed) ----
__device__ __half    g_msg_h[N_NODES * HID];  // dinv[v] * (x @ W_gcn)[v]  (fp16)
__device__ float     g_dinv[N_NODES];
__device__ int       g_ecnt[N_NODES];         // in-degree (excl. self-loop)
__device__ int       g_off[N_NODES];          // CSR offsets
__device__ int       g_cursor[N_NODES];       // scatter cursors
__device__ int       g_bsum[N_SBLK];          // scan block sums
__device__ unsigned  g_psrc[N_EDGES];         // src index per edge, sorted by target
__device__ float     g_sums[N_GRAPHS * HID];
__device__ float     g_cnts[N_GRAPHS];

__device__ __forceinline__ void red_add_v2(float* p, float2 v) {
    asm volatile("red.global.add.v2.f32 [%0], {%1,%2};"
                 :: "l"(p), "f"(v.x), "f"(v.y) : "memory");
}

__device__ __forceinline__ unsigned f2_to_h2(float2 f) {
    __half2 h = __floats2half2_rn(f.x, f.y);
    return *(unsigned*)&h;
}

// ---- init ----
__global__ void init_kernel() {
    int i = blockIdx.x * blockDim.x + threadIdx.x;
    if (i < N_NODES) g_ecnt[i] = 0;
    if (i < N_GRAPHS * HID) g_sums[i] = 0.0f;
    if (i < N_GRAPHS) g_cnts[i] = 0.0f;
}

// ---- in-degree over target nodes, 4 edges per thread ----
__global__ void deg_kernel(const int* __restrict__ ei) {
    int i = blockIdx.x * blockDim.x + threadIdx.x;
    if (i < N_EDGES / 4) {
        int4 c = ((const int4*)(ei + N_EDGES))[i];
        atomicAdd(&g_ecnt[c.x], 1);
        atomicAdd(&g_ecnt[c.y], 1);
        atomicAdd(&g_ecnt[c.z], 1);
        atomicAdd(&g_ecnt[c.w], 1);
    }
}

__global__ void dinv_kernel() {
    int i = blockIdx.x * blockDim.x + threadIdx.x;
    if (i < N_NODES) g_dinv[i] = rsqrtf(1.0f + (float)g_ecnt[i]);  // +1 self-loop
}

// ---- prefix scan of g_ecnt -> g_off (3 stages) ----
__global__ __launch_bounds__(1024) void scan1_kernel() {
    __shared__ int sh[1024];
    int i = blockIdx.x * 1024 + threadIdx.x;
    sh[threadIdx.x] = (i < N_NODES) ? g_ecnt[i] : 0;
    __syncthreads();
    for (int d = 512; d > 0; d >>= 1) {
        if (threadIdx.x < d) sh[threadIdx.x] += sh[threadIdx.x + d];
        __syncthreads();
    }
    if (threadIdx.x == 0) g_bsum[blockIdx.x] = sh[0];
}

__global__ __launch_bounds__(128) void scan2_kernel() {
    __shared__ int sh[128];
    int t = threadIdx.x;
    int v = (t < N_SBLK) ? g_bsum[t] : 0;
    sh[t] = v;
    __syncthreads();
    for (int d = 1; d < 128; d <<= 1) {
        int tmp = (t >= d) ? sh[t - d] : 0;
        __syncthreads();
        sh[t] += tmp;
        __syncthreads();
    }
    if (t < N_SBLK) g_bsum[t] = sh[t] - v;  // exclusive base
}

__global__ __launch_bounds__(1024) void scan3_kernel() {
    __shared__ int sh[1024];
    int i = blockIdx.x * 1024 + threadIdx.x;
    int v = (i < N_NODES) ? g_ecnt[i] : 0;
    sh[threadIdx.x] = v;
    __syncthreads();
    for (int d = 1; d < 1024; d <<= 1) {
        int tmp = (threadIdx.x >= d) ? sh[threadIdx.x - d] : 0;
        __syncthreads();
        sh[threadIdx.x] += tmp;
        __syncthreads();
    }
    if (i < N_NODES) {
        int off = g_bsum[blockIdx.x] + sh[threadIdx.x] - v;
        g_off[i] = off;
        g_cursor[i] = off;
    }
}

// ---- scatter edges into CSR buckets: src index only (norm factorized out) ----
__global__ void scatter_kernel(const int* __restrict__ ei) {
    int e = blockIdx.x * blockDim.x + threadIdx.x;
    if (e >= N_EDGES) return;
    int r = __ldg(&ei[e]);
    int c = __ldg(&ei[N_EDGES + e]);
    int pos = atomicAdd(&g_cursor[c], 1);
    g_psrc[pos] = (unsigned)r;
}

// ---- tensor-core GEMM: msg = dinv * (x @ W_gcn), fp16 out ----
// mma.m16n8k16 f32.f16.f16.f32; 8 warps x 16 rows = 128 rows/block, N=64, K=128.
__global__ __launch_bounds__(256) void gemm_kernel(const float* __restrict__ x,
                                                   const float* __restrict__ W) {
    __shared__ __half Bs[HID][136];  // W transposed [n][k], padded: banks (4g+tig) distinct

    const int tid = threadIdx.x;
    {   // load + transpose + convert W: thread t covers k = t>>1, 32 n values
        int k  = tid >> 1;
        int nh = (tid & 1) * 32;
        #pragma unroll 8
        for (int j = 0; j < 32; j++)
            Bs[nh + j][k] = __float2half_rn(__ldg(&W[k * HID + nh + j]));
    }
    __syncthreads();

    const int wid  = tid >> 5, lane = tid & 31;
    const int g    = lane >> 2, tig = lane & 3;
    const int row  = blockIdx.x * 128 + wid * 16 + g;     // rows: row, row+8
    const int r0   = min(row, N_NODES - 1);
    const int r8   = min(row + 8, N_NODES - 1);
    const float* x0 = x + (size_t)r0 * IN_DIM + tig * 2;
    const float* x8 = x + (size_t)r8 * IN_DIM + tig * 2;

    float c[8][4] = {};

    #pragma unroll
    for (int kt = 0; kt < 8; kt++) {
        const int kb = kt * 16;
        unsigned a0 = f2_to_h2(__ldg((const float2*)(x0 + kb)));
        unsigned a1 = f2_to_h2(__ldg((const float2*)(x8 + kb)));
        unsigned a2 = f2_to_h2(__ldg((const float2*)(x0 + kb + 8)));
        unsigned a3 = f2_to_h2(__ldg((const float2*)(x8 + kb + 8)));
        #pragma unroll
        for (int nt = 0; nt < 8; nt++) {
            unsigned b0 = *(const unsigned*)&Bs[nt * 8 + g][kb + tig * 2];
            unsigned b1 = *(const unsigned*)&Bs[nt * 8 + g][kb + tig * 2 + 8];
            asm volatile(
                "mma.sync.aligned.m16n8k16.row.col.f32.f16.f16.f32 "
                "{%0,%1,%2,%3}, {%4,%5,%6,%7}, {%8,%9}, {%0,%1,%2,%3};"
                : "+f"(c[nt][0]), "+f"(c[nt][1]), "+f"(c[nt][2]), "+f"(c[nt][3])
                : "r"(a0), "r"(a1), "r"(a2), "r"(a3), "r"(b0), "r"(b1));
        }
    }

    const float d0 = g_dinv[r0] ;
    const float d8 = g_dinv[r8];
    const bool  v0 = row < N_NODES;
    const bool  v8 = row + 8 < N_NODES;
    #pragma unroll
    for (int nt = 0; nt < 8; nt++) {
        int col = nt * 8 + tig * 2;
        if (v0) *(unsigned*)&g_msg_h[(size_t)row * HID + col] =
            f2_to_h2(make_float2(c[nt][0] * d0, c[nt][1] * d0));
        if (v8) *(unsigned*)&g_msg_h[(size_t)(row + 8) * HID + col] =
            f2_to_h2(make_float2(c[nt][2] * d8, c[nt][3] * d8));
    }
}

// ---- aggregate + scale + bias + relu + mean-pool fused; warp per node ----
__global__ __launch_bounds__(256) void aggregate_kernel(const int* __restrict__ batch,
                                                        const float* __restrict__ b_gcn) {
    int n = blockIdx.x * 8 + (threadIdx.x >> 5);
    int lane = threadIdx.x & 31;
    if (n >= N_NODES) return;

    int start = __ldg(&g_off[n]);
    int cnt   = __ldg(&g_ecnt[n]);

    // self-loop: z = dinv[n] * (... + msg[n])
    unsigned sv = __ldg((const unsigned*)(g_msg_h + ((size_t)n << 6)) + lane);
    float2 acc = __half22float2(*(__half2*)&sv);

    for (int base = 0; base < cnt; base += 32) {
        int m = cnt - base; if (m > 32) m = 32;
        unsigned r = 0;
        if (lane < m) r = __ldg(&g_psrc[start + base + lane]);
        if (m == 32) {
            #pragma unroll
            for (int j = 0; j < 32; j++) {
                unsigned rj = __shfl_sync(0xffffffffu, r, j);
                unsigned rv = __ldg((const unsigned*)(g_msg_h + ((size_t)rj << 6)) + lane);
                float2 f = __half22float2(*(__half2*)&rv);
                acc.x += f.x; acc.y += f.y;
            }
        } else {
            for (int j = 0; j < m; j++) {
                unsigned rj = __shfl_sync(0xffffffffu, r, j);
                unsigned rv = __ldg((const unsigned*)(g_msg_h + ((size_t)rj << 6)) + lane);
                float2 f = __half22float2(*(__half2*)&rv);
                acc.x += f.x; acc.y += f.y;
            }
        }
    }

    float dc = g_dinv[n];
    float2 b = __ldg(&((const float2*)b_gcn)[lane]);
    acc.x = fmaxf(acc.x * dc + b.x, 0.0f);
    acc.y = fmaxf(acc.y * dc + b.y, 0.0f);

    int g = __ldg(&batch[n]);
    red_add_v2(&g_sums[(size_t)g * HID + lane * 2], acc);
    if (lane == 0) atomicAdd(&g_cnts[g], 1.0f);
}

// ---- per-graph MLP: relu(g@W1+b1) @ W2 + b2 -> sigmoid ----
__global__ __launch_bounds__(64) void mlp_kernel(const float* __restrict__ W1,
                                                 const float* __restrict__ b1,
                                                 const float* __restrict__ W2,
                                                 const float* __restrict__ b2,
                                                 float* __restrict__ out) {
    int g = blockIdx.x;
    int c = threadIdx.x;
    __shared__ float gs[HID], hs[HID];

    float cnt = fmaxf(g_cnts[g], 1.0f);
    gs[c] = g_sums[(size_t)g * HID + c] / cnt;
    __syncthreads();

    float acc = b1[c];
    #pragma unroll 8
    for (int k = 0; k < HID; k++) acc += gs[k] * W1[k * HID + c];
    hs[c] = fmaxf(acc, 0.0f);
    __syncthreads();

    if (c < 2) {
        float a = b2[c];
        #pragma unroll 8
        for (int k = 0; k < HID; k++) a += hs[k] * W2[k * 2 + c];
        out[(size_t)g * 2 + c] = 1.0f / (1.0f + expf(-a));
    }
}

extern "C" void kernel_launch(void* const* d_in, const int* in_sizes, int n_in,
                              void* d_out, int out_size) {
    const float* x     = (const float*)d_in[0];
    const int*   ei    = (const int*)d_in[1];
    const int*   batch = (const int*)d_in[2];
    const float* W_gcn = (const float*)d_in[3];
    const float* b_gcn = (const float*)d_in[4];
    const float* W1    = (const float*)d_in[5];
    const float* b1    = (const float*)d_in[6];
    const float* W2    = (const float*)d_in[7];
    const float* b2    = (const float*)d_in[8];
    float*       out   = (float*)d_out;

    init_kernel<<<(N_NODES + 255) / 256, 256>>>();
    deg_kernel<<<(N_EDGES / 4 + 255) / 256, 256>>>(ei);
    dinv_kernel<<<(N_NODES + 255) / 256, 256>>>();
    scan1_kernel<<<N_SBLK, 1024>>>();
    scan2_kernel<<<1, 128>>>();
    scan3_kernel<<<N_SBLK, 1024>>>();
    scatter_kernel<<<(N_EDGES + 255) / 256, 256>>>(ei);
    gemm_kernel<<<(N_NODES + 127) / 128, 256>>>(x, W_gcn);
    aggregate_kernel<<<(N_NODES + 7) / 8, 256>>>(batch, b_gcn);
    mlp_kernel<<<N_GRAPHS, 64>>>(W1, b1, W2, b2, out);
}

// round 6
// speedup vs baseline: 1.7477x; 1.0771x over previous
#include <cuda_runtime.h>
#include <cuda_fp16.h>

#define N_NODES 100000
#define N_EDGES 3200000
#define IN_DIM 128
#define HID 64
#define N_GRAPHS 512
#define N_SBLK 98   // ceil(N_NODES / 1024)

// ---- scratch (static device globals; no allocation allowed) ----
__device__ __half    g_msg_h[N_NODES * HID];  // dinv[v] * (x @ W_gcn)[v]  (fp16)
__device__ float     g_dinv[N_NODES];
__device__ int       g_ecnt[N_NODES];         // in-degree (excl. self-loop)
__device__ int       g_off[N_NODES];          // CSR offsets
__device__ int       g_cursor[N_NODES];       // scatter cursors
__device__ int       g_bsum[N_SBLK];          // scan block sums
__device__ unsigned  g_psrc[N_EDGES];         // src index per edge, sorted by target
__device__ float     g_sums[N_GRAPHS * HID];
__device__ float     g_cnts[N_GRAPHS];

__device__ __forceinline__ void red_add_v4(float* p, float4 v) {
    asm volatile("red.global.add.v4.f32 [%0], {%1,%2,%3,%4};"
                 :: "l"(p), "f"(v.x), "f"(v.y), "f"(v.z), "f"(v.w) : "memory");
}

__device__ __forceinline__ unsigned f2_to_h2(float2 f) {
    __half2 h = __floats2half2_rn(f.x, f.y);
    return *(unsigned*)&h;
}

// ---- init ----
__global__ void init_kernel() {
    int i = blockIdx.x * blockDim.x + threadIdx.x;
    if (i < N_NODES) g_ecnt[i] = 0;
    if (i < N_GRAPHS * HID) g_sums[i] = 0.0f;
    if (i < N_GRAPHS) g_cnts[i] = 0.0f;
}

// ---- in-degree over target nodes, 4 edges per thread ----
__global__ void deg_kernel(const int* __restrict__ ei) {
    int i = blockIdx.x * blockDim.x + threadIdx.x;
    if (i < N_EDGES / 4) {
        int4 c = ((const int4*)(ei + N_EDGES))[i];
        atomicAdd(&g_ecnt[c.x], 1);
        atomicAdd(&g_ecnt[c.y], 1);
        atomicAdd(&g_ecnt[c.z], 1);
        atomicAdd(&g_ecnt[c.w], 1);
    }
}

// ---- scan stage 1: block sums (warp-shuffle reduce, 1 sync) ----
__global__ __launch_bounds__(1024) void scan1_kernel() {
    __shared__ int ws[32];
    int i = blockIdx.x * 1024 + threadIdx.x;
    int s = (i < N_NODES) ? g_ecnt[i] : 0;
    #pragma unroll
    for (int d = 16; d; d >>= 1) s += __shfl_down_sync(0xffffffffu, s, d);
    int wid = threadIdx.x >> 5, lane = threadIdx.x & 31;
    if (lane == 0) ws[wid] = s;
    __syncthreads();
    if (wid == 0) {
        int t = ws[lane];
        #pragma unroll
        for (int d = 16; d; d >>= 1) t += __shfl_down_sync(0xffffffffu, t, d);
        if (lane == 0) g_bsum[blockIdx.x] = t;
    }
}

// ---- scan stage 2: exclusive scan of 98 block sums ----
__global__ __launch_bounds__(128) void scan2_kernel() {
    __shared__ int sh[128];
    int t = threadIdx.x;
    int v = (t < N_SBLK) ? g_bsum[t] : 0;
    sh[t] = v;
    __syncthreads();
    for (int d = 1; d < 128; d <<= 1) {
        int tmp = (t >= d) ? sh[t - d] : 0;
        __syncthreads();
        sh[t] += tmp;
        __syncthreads();
    }
    if (t < N_SBLK) g_bsum[t] = sh[t] - v;  // exclusive base
}

// ---- scan stage 3: per-block inclusive scan (shuffles) + offsets + dinv ----
__global__ __launch_bounds__(1024) void scan3_kernel() {
    __shared__ int ws[32];
    int i = blockIdx.x * 1024 + threadIdx.x;
    int lane = threadIdx.x & 31, wid = threadIdx.x >> 5;
    int v = (i < N_NODES) ? g_ecnt[i] : 0;
    int inc = v;
    #pragma unroll
    for (int d = 1; d < 32; d <<= 1) {
        int t = __shfl_up_sync(0xffffffffu, inc, d);
        if (lane >= d) inc += t;
    }
    if (lane == 31) ws[wid] = inc;
    __syncthreads();
    if (wid == 0) {
        int t = ws[lane];
        #pragma unroll
        for (int d = 1; d < 32; d <<= 1) {
            int u = __shfl_up_sync(0xffffffffu, t, d);
            if (lane >= d) t += u;
        }
        ws[lane] = t;
    }
    __syncthreads();
    if (i < N_NODES) {
        int base = g_bsum[blockIdx.x] + (wid ? ws[wid - 1] : 0);
        int off = base + inc - v;   // exclusive
        g_off[i]    = off;
        g_cursor[i] = off;
        g_dinv[i]   = rsqrtf(1.0f + (float)v);  // +1 self-loop
    }
}

// ---- scatter edges into CSR buckets: src index only (norm factorized out) ----
__global__ void scatter_kernel(const int* __restrict__ ei) {
    int e = blockIdx.x * blockDim.x + threadIdx.x;
    if (e >= N_EDGES) return;
    int r = __ldg(&ei[e]);
    int c = __ldg(&ei[N_EDGES + e]);
    int pos = atomicAdd(&g_cursor[c], 1);
    g_psrc[pos] = (unsigned)r;
}

// ---- tensor-core GEMM: msg = dinv * (x @ W_gcn), fp16 out ----
__global__ __launch_bounds__(256) void gemm_kernel(const float* __restrict__ x,
                                                   const float* __restrict__ W) {
    __shared__ __half Bs[HID][136];  // W transposed [n][k], padded

    const int tid = threadIdx.x;
    {
        int k  = tid >> 1;
        int nh = (tid & 1) * 32;
        #pragma unroll 8
        for (int j = 0; j < 32; j++)
            Bs[nh + j][k] = __float2half_rn(__ldg(&W[k * HID + nh + j]));
    }
    __syncthreads();

    const int wid  = tid >> 5, lane = tid & 31;
    const int g    = lane >> 2, tig = lane & 3;
    const int row  = blockIdx.x * 128 + wid * 16 + g;
    const int r0   = min(row, N_NODES - 1);
    const int r8   = min(row + 8, N_NODES - 1);
    const float* x0 = x + (size_t)r0 * IN_DIM + tig * 2;
    const float* x8 = x + (size_t)r8 * IN_DIM + tig * 2;

    float c[8][4] = {};

    #pragma unroll
    for (int kt = 0; kt < 8; kt++) {
        const int kb = kt * 16;
        unsigned a0 = f2_to_h2(__ldg((const float2*)(x0 + kb)));
        unsigned a1 = f2_to_h2(__ldg((const float2*)(x8 + kb)));
        unsigned a2 = f2_to_h2(__ldg((const float2*)(x0 + kb + 8)));
        unsigned a3 = f2_to_h2(__ldg((const float2*)(x8 + kb + 8)));
        #pragma unroll
        for (int nt = 0; nt < 8; nt++) {
            unsigned b0 = *(const unsigned*)&Bs[nt * 8 + g][kb + tig * 2];
            unsigned b1 = *(const unsigned*)&Bs[nt * 8 + g][kb + tig * 2 + 8];
            asm volatile(
                "mma.sync.aligned.m16n8k16.row.col.f32.f16.f16.f32 "
                "{%0,%1,%2,%3}, {%4,%5,%6,%7}, {%8,%9}, {%0,%1,%2,%3};"
                : "+f"(c[nt][0]), "+f"(c[nt][1]), "+f"(c[nt][2]), "+f"(c[nt][3])
                : "r"(a0), "r"(a1), "r"(a2), "r"(a3), "r"(b0), "r"(b1));
        }
    }

    const float d0 = g_dinv[r0];
    const float d8 = g_dinv[r8];
    const bool  v0 = row < N_NODES;
    const bool  v8 = row + 8 < N_NODES;
    #pragma unroll
    for (int nt = 0; nt < 8; nt++) {
        int col = nt * 8 + tig * 2;
        if (v0) *(unsigned*)&g_msg_h[(size_t)row * HID + col] =
            f2_to_h2(make_float2(c[nt][0] * d0, c[nt][1] * d0));
        if (v8) *(unsigned*)&g_msg_h[(size_t)(row + 8) * HID + col] =
            f2_to_h2(make_float2(c[nt][2] * d8, c[nt][3] * d8));
    }
}

// ---- aggregate + scale + bias + relu + mean-pool fused ----
// Persistent warp-stride over nodes; 2 edges per warp-step via half-warps.
// Lane layout: half = lane>>4, sub = lane&15; lane covers cols [4*sub, 4*sub+4).
__global__ __launch_bounds__(256) void aggregate_kernel(const int* __restrict__ batch,
                                                        const float* __restrict__ b_gcn) {
    const int warps_total = gridDim.x * 8;
    const int wglobal = blockIdx.x * 8 + (threadIdx.x >> 5);
    const int lane = threadIdx.x & 31;
    const int sub  = lane & 15;
    const int hb   = lane & 16;       // 0 for half A, 16 for half B
    const float4 bb = __ldg(&((const float4*)b_gcn)[sub]);

    for (int n = wglobal; n < N_NODES; n += warps_total) {
        int start = __ldg(&g_off[n]);
        int cnt   = __ldg(&g_ecnt[n]);

        float4 acc = make_float4(0.f, 0.f, 0.f, 0.f);
        if (hb == 0) {  // self-loop term on half A
            uint2 rv = __ldg((const uint2*)(g_msg_h + ((size_t)n << 6)) + sub);
            float2 f0 = __half22float2(*(__half2*)&rv.x);
            float2 f1 = __half22float2(*(__half2*)&rv.y);
            acc = make_float4(f0.x, f0.y, f1.x, f1.y);
        }

        for (int base = 0; base < cnt; base += 32) {
            int m = cnt - base; if (m > 32) m = 32;
            unsigned r = 0;
            if (lane < m) r = __ldg(&g_psrc[start + base + lane]);
            if (m == 32) {
                #pragma unroll
                for (int j = 0; j < 16; j++) {
                    unsigned rj = __shfl_sync(0xffffffffu, r, hb + j);
                    uint2 rv = __ldg((const uint2*)(g_msg_h + ((size_t)rj << 6)) + sub);
                    float2 f0 = __half22float2(*(__half2*)&rv.x);
                    float2 f1 = __half22float2(*(__half2*)&rv.y);
                    acc.x += f0.x; acc.y += f0.y; acc.z += f1.x; acc.w += f1.y;
                }
            } else {
                int jlim = (m < 16) ? m : 16;
                for (int j = 0; j < jlim; j++) {
                    unsigned rj = __shfl_sync(0xffffffffu, r, hb + j);
                    if (hb + j < m) {
                        uint2 rv = __ldg((const uint2*)(g_msg_h + ((size_t)rj << 6)) + sub);
                        float2 f0 = __half22float2(*(__half2*)&rv.x);
                        float2 f1 = __half22float2(*(__half2*)&rv.y);
                        acc.x += f0.x; acc.y += f0.y; acc.z += f1.x; acc.w += f1.y;
                    }
                }
            }
        }

        // combine halves
        acc.x += __shfl_xor_sync(0xffffffffu, acc.x, 16);
        acc.y += __shfl_xor_sync(0xffffffffu, acc.y, 16);
        acc.z += __shfl_xor_sync(0xffffffffu, acc.z, 16);
        acc.w += __shfl_xor_sync(0xffffffffu, acc.w, 16);

        float dc = g_dinv[n];
        acc.x = fmaxf(acc.x * dc + bb.x, 0.f);
        acc.y = fmaxf(acc.y * dc + bb.y, 0.f);
        acc.z = fmaxf(acc.z * dc + bb.z, 0.f);
        acc.w = fmaxf(acc.w * dc + bb.w, 0.f);

        int g = __ldg(&batch[n]);
        if (lane < 16) red_add_v4(&g_sums[(size_t)g * HID + sub * 4], acc);
        if (lane == 0) atomicAdd(&g_cnts[g], 1.0f);
    }
}

// ---- per-graph MLP: relu(g@W1+b1) @ W2 + b2 -> sigmoid ----
__global__ __launch_bounds__(64) void mlp_kernel(const float* __restrict__ W1,
                                                 const float* __restrict__ b1,
                                                 const float* __restrict__ W2,
                                                 const float* __restrict__ b2,
                                                 float* __restrict__ out) {
    int g = blockIdx.x;
    int c = threadIdx.x;
    __shared__ float gs[HID], hs[HID];

    float cnt = fmaxf(g_cnts[g], 1.0f);
    gs[c] = g_sums[(size_t)g * HID + c] / cnt;
    __syncthreads();

    float acc = b1[c];
    #pragma unroll 8
    for (int k = 0; k < HID; k++) acc += gs[k] * W1[k * HID + c];
    hs[c] = fmaxf(acc, 0.0f);
    __syncthreads();

    if (c < 2) {
        float a = b2[c];
        #pragma unroll 8
        for (int k = 0; k < HID; k++) a += hs[k] * W2[k * 2 + c];
        out[(size_t)g * 2 + c] = 1.0f / (1.0f + expf(-a));
    }
}

extern "C" void kernel_launch(void* const* d_in, const int* in_sizes, int n_in,
                              void* d_out, int out_size) {
    const float* x     = (const float*)d_in[0];
    const int*   ei    = (const int*)d_in[1];
    const int*   batch = (const int*)d_in[2];
    const float* W_gcn = (const float*)d_in[3];
    const float* b_gcn = (const float*)d_in[4];
    const float* W1    = (const float*)d_in[5];
    const float* b1    = (const float*)d_in[6];
    const float* W2    = (const float*)d_in[7];
    const float* b2    = (const float*)d_in[8];
    float*       out   = (float*)d_out;

    init_kernel<<<(N_NODES + 255) / 256, 256>>>();
    deg_kernel<<<(N_EDGES / 4 + 255) / 256, 256>>>(ei);
    scan1_kernel<<<N_SBLK, 1024>>>();
    scan2_kernel<<<1, 128>>>();
    scan3_kernel<<<N_SBLK, 1024>>>();
    scatter_kernel<<<(N_EDGES + 255) / 256, 256>>>(ei);
    gemm_kernel<<<(N_NODES + 127) / 128, 256>>>(x, W_gcn);
    aggregate_kernel<<<1184, 256>>>(batch, b_gcn);
    mlp_kernel<<<N_GRAPHS, 64>>>(W1, b1, W2, b2, out);
}